// round 4
// baseline (speedup 1.0000x reference)
#include <cuda_runtime.h>
#include <cuda_bf16.h>

// Problem constants (fixed shapes)
#define TN1 32768
#define TN2 32768
#define TDEG 16
#define TIN 128
#define TH 8
#define TD 16
#define THD 128           // H*D
#define TE (TN2*TDEG)     // 524288 edges

#define AP 132            // padded smem pitch (floats) for A tiles

// Scratch for projected Q/K/V (48 MB total, static device arrays are allowed)
__device__ float g_Q[TN2*THD];
__device__ float g_K[TN1*THD];
__device__ float g_V[TN1*THD];

// ---------------------------------------------------------------------------
// Phase 1: Q/K/V = x @ {wq,wk,wv}.  One block = 128 rows x 128 cols x K=128.
// ---------------------------------------------------------------------------
__global__ __launch_bounds__(256, 1)
void qkv_kernel(const float* __restrict__ x,
                const float* __restrict__ wq,
                const float* __restrict__ wk,
                const float* __restrict__ wv)
{
    extern __shared__ float sm[];
    float* sW = sm;               // 128*128 weight tile
    float* sA = sm + 128*128;     // 128 rows * AP x tile

    const float* w   = (blockIdx.y == 0) ? wq  : (blockIdx.y == 1) ? wk  : wv;
    float*       dst = (blockIdx.y == 0) ? g_Q : (blockIdx.y == 1) ? g_K : g_V;

    const int tid  = threadIdx.x;
    const int row0 = blockIdx.x * 128;

    {
        const float4* w4 = (const float4*)w;
        float4* s4 = (float4*)sW;
#pragma unroll
        for (int i = 0; i < 16; i++) s4[tid + i*256] = w4[tid + i*256];
    }
#pragma unroll
    for (int c = 0; c < 16; c++) {
        int f4 = c*256 + tid;
        int r  = f4 >> 5;
        int k4 = f4 & 31;
        float4 v = *(const float4*)(x + (size_t)(row0 + r)*TIN + k4*4);
        *(float4*)(sA + r*AP + k4*4) = v;
    }
    __syncthreads();

    const int ty = tid >> 4, tx = tid & 15;
    float acc[8][8];
#pragma unroll
    for (int i = 0; i < 8; i++)
#pragma unroll
        for (int j = 0; j < 8; j++) acc[i][j] = 0.f;

    const float* aBase = sA + ty*8*AP;
    const float* bBase = sW + tx*8;

#pragma unroll 1
    for (int k = 0; k < 128; k += 4) {
        float a_[8][4];
#pragma unroll
        for (int i = 0; i < 8; i++) {
            float4 t = *(const float4*)(aBase + i*AP + k);
            a_[i][0] = t.x; a_[i][1] = t.y; a_[i][2] = t.z; a_[i][3] = t.w;
        }
#pragma unroll
        for (int kk = 0; kk < 4; kk++) {
            float4 b0 = *(const float4*)(bBase + (k+kk)*128);
            float4 b1 = *(const float4*)(bBase + (k+kk)*128 + 4);
            float bv[8] = {b0.x,b0.y,b0.z,b0.w,b1.x,b1.y,b1.z,b1.w};
#pragma unroll
            for (int i = 0; i < 8; i++) {
                float av = a_[i][kk];
#pragma unroll
                for (int j = 0; j < 8; j++) acc[i][j] = fmaf(av, bv[j], acc[i][j]);
            }
        }
    }

#pragma unroll
    for (int i = 0; i < 8; i++) {
        float* o = dst + (size_t)(row0 + ty*8 + i)*THD + tx*8;
        *(float4*)(o)     = make_float4(acc[i][0], acc[i][1], acc[i][2], acc[i][3]);
        *(float4*)(o + 4) = make_float4(acc[i][4], acc[i][5], acc[i][6], acc[i][7]);
    }
}

// ---------------------------------------------------------------------------
// Phase 2: fused per-node-tile attention (faithful to the torch reshape bug).
// score[n,h',d'] = sum_k e1[n, dd, hh, k]*K[nbr(n,dd)][hh,k]*q[n,h',k] + e2[n,d',h']
//   where dd = 2*h' + d'/8, hh = d' % 8   (the [n2,deg,H,D]->[n2*H,deg,D] reshape)
// ---------------------------------------------------------------------------
__global__ __launch_bounds__(256, 1)
void attn_kernel(const float* __restrict__ ea,
                 const float* __restrict__ we1,
                 const float* __restrict__ we2,
                 const float* __restrict__ be2,
                 const int* __restrict__ eidx,     // int32 on the wire
                 float* __restrict__ outp)
{
    extern __shared__ float sm[];
    float* sW  = sm;                   // 16384  : we1
    float* sA  = sW + 16384;           // 128*AP : edge_attr tile, later e1 (pitch 128)
    float* sW2 = sA + 128*AP;          // 1024   : we2 (128x8)
    float* sQ  = sW2 + 1024;           // 1024   : q rows for 8 nodes
    float* sE2 = sQ + 1024;            // 1024   : e2 [128 edges][8 h]
    float* sSc = sE2 + 1024;           // 1024   : scores/attn [8 node][8 h'][16 d']
    int*   sNbr = (int*)(sSc + 1024);  // 128    : neighbor ids

    const int tid   = threadIdx.x;
    const int node0 = blockIdx.x * 8;
    const int e0    = node0 * TDEG;

    // ---- stage inputs ----
    {
        const float4* w4 = (const float4*)we1;
        float4* s4 = (float4*)sW;
#pragma unroll
        for (int i = 0; i < 16; i++) s4[tid + i*256] = w4[tid + i*256];
    }
    ((float4*)sW2)[tid] = ((const float4*)we2)[tid];
    ((float4*)sQ)[tid]  = ((const float4*)(g_Q + (size_t)node0*THD))[tid];
    if (tid < 128) sNbr[tid] = eidx[e0 + tid];
#pragma unroll
    for (int c = 0; c < 16; c++) {
        int f4 = c*256 + tid;
        int r  = f4 >> 5;
        int k4 = f4 & 31;
        float4 v = *(const float4*)(ea + (size_t)(e0 + r)*TIN + k4*4);
        *(float4*)(sA + r*AP + k4*4) = v;
    }
    __syncthreads();

    // ---- e1 GEMM (register tile 8x8) + e2 folded in ----
    const int ty = tid >> 4, tx = tid & 15;
    const int htx = tx & 7;
    float acc[8][8];
    float e2a[8];
#pragma unroll
    for (int i = 0; i < 8; i++) {
        e2a[i] = 0.f;
#pragma unroll
        for (int j = 0; j < 8; j++) acc[i][j] = 0.f;
    }

    const float* aBase = sA + ty*8*AP;
    const float* bBase = sW + tx*8;

#pragma unroll 1
    for (int k = 0; k < 128; k += 4) {
        float a_[8][4];
#pragma unroll
        for (int i = 0; i < 8; i++) {
            float4 t = *(const float4*)(aBase + i*AP + k);
            a_[i][0] = t.x; a_[i][1] = t.y; a_[i][2] = t.z; a_[i][3] = t.w;
        }
#pragma unroll
        for (int kk = 0; kk < 4; kk++) {
            float4 b0 = *(const float4*)(bBase + (k+kk)*128);
            float4 b1 = *(const float4*)(bBase + (k+kk)*128 + 4);
            float w2v = sW2[(k+kk)*TH + htx];
            float bv[8] = {b0.x,b0.y,b0.z,b0.w,b1.x,b1.y,b1.z,b1.w};
#pragma unroll
            for (int i = 0; i < 8; i++) {
                float av = a_[i][kk];
                e2a[i] = fmaf(av, w2v, e2a[i]);
#pragma unroll
                for (int j = 0; j < 8; j++) acc[i][j] = fmaf(av, bv[j], acc[i][j]);
            }
        }
    }
    __syncthreads();   // done reading sA (edge_attr)

    // write e1 into sA (pitch 128), write e2 (+bias)
#pragma unroll
    for (int i = 0; i < 8; i++) {
        float* o = sA + (ty*8 + i)*128 + tx*8;
        *(float4*)(o)     = make_float4(acc[i][0], acc[i][1], acc[i][2], acc[i][3]);
        *(float4*)(o + 4) = make_float4(acc[i][4], acc[i][5], acc[i][6], acc[i][7]);
    }
    if (tx < 8) {
        float b = be2[htx];
#pragma unroll
        for (int i = 0; i < 8; i++) sE2[(ty*8 + i)*TH + htx] = e2a[i] + b;
    }
    __syncthreads();

    // ---- scores: 1024 (nl, h', d') tuples, 4 per thread ----
    // torch-reshape mapping: e1/K slice uses (dd = 2h' + d'/8, hh = d'%8); q uses h'
#pragma unroll
    for (int s = 0; s < 4; s++) {
        int u  = tid + s*256;
        int dp = u & 15;            // d'
        int hp = (u >> 4) & 7;      // h'
        int nl = u >> 7;            // local node 0..7
        int dd = 2*hp + (dp >> 3);  // deg index used by e1*k
        int hh = dp & 7;            // head index used by e1*k
        int edge_b = nl*16 + dd;
        int nbr = sNbr[edge_b];
        const float* kp = g_K + (size_t)nbr*THD + hh*TD;
        const float* ep = sA + edge_b*128 + hh*TD;
        const float* qp = sQ + nl*THD + hp*TD;
        float sc = sE2[(nl*16 + dp)*TH + hp];   // e2 is a clean transpose: (deg=d', head=h')
#pragma unroll
        for (int d = 0; d < TD; d += 4) {
            float4 kv = *(const float4*)(kp + d);
            float4 ev = *(const float4*)(ep + d);
            float4 qv = *(const float4*)(qp + d);
            sc += ev.x*kv.x*qv.x;
            sc += ev.y*kv.y*qv.y;
            sc += ev.z*kv.z*qv.z;
            sc += ev.w*kv.w*qv.w;
        }
        sc = fminf(8.0f, fmaxf(-8.0f, sc));
        sSc[nl*128 + hp*16 + dp] = sc;
    }
    __syncthreads();

    // ---- softmax over d'=16, one thread per (node, h') ----
    if (tid < 64) {
        int nl = tid >> 3, h = tid & 7;
        float* p = sSc + nl*128 + h*16;
        float m = p[0];
#pragma unroll
        for (int e = 1; e < 16; e++) m = fmaxf(m, p[e]);
        float ssum = 0.f;
#pragma unroll
        for (int e = 0; e < 16; e++) { float t = __expf(p[e] - m); p[e] = t; ssum += t; }
        float inv = 1.0f / ssum;
#pragma unroll
        for (int e = 0; e < 16; e++) p[e] *= inv;
    }
    __syncthreads();

    // ---- output (clean einsum): out[n,h,k] = sum_d' attn[n,h,d'] * V[nbr(n,d')][h,k] ----
#pragma unroll
    for (int s = 0; s < 4; s++) {
        int u  = tid + s*256;
        int nl = u >> 7;
        int hd = u & 127;
        int h  = hd >> 4;
        const float* ap = sSc + nl*128 + h*16;
        float acco = 0.f;
#pragma unroll
        for (int e = 0; e < 16; e++) {
            int nbr = sNbr[nl*16 + e];
            acco = fmaf(ap[e], g_V[(size_t)nbr*THD + hd], acco);
        }
        outp[(size_t)(node0 + nl)*THD + hd] = acco;
    }
}

// ---------------------------------------------------------------------------
// Launch
// ---------------------------------------------------------------------------
extern "C" void kernel_launch(void* const* d_in, const int* in_sizes, int n_in,
                              void* d_out, int out_size)
{
    const float* x    = (const float*)d_in[0];
    const float* ea   = (const float*)d_in[1];
    const float* wq   = (const float*)d_in[2];
    const float* wk   = (const float*)d_in[3];
    const float* wv   = (const float*)d_in[4];
    const float* we1  = (const float*)d_in[5];
    const float* we2  = (const float*)d_in[6];
    const float* be2  = (const float*)d_in[7];
    const int*   eidx = (const int*)d_in[8];
    float*       outp = (float*)d_out;

    const int SMEM_QKV = (128*128 + 128*AP) * 4;
    const int SMEM_ATT = (16384 + 128*AP + 1024*4) * 4 + 128*4;

    cudaFuncSetAttribute(qkv_kernel,  cudaFuncAttributeMaxDynamicSharedMemorySize, SMEM_QKV);
    cudaFuncSetAttribute(attn_kernel, cudaFuncAttributeMaxDynamicSharedMemorySize, SMEM_ATT);

    qkv_kernel<<<dim3(TN1/128, 3), 256, SMEM_QKV>>>(x, wq, wk, wv);
    attn_kernel<<<TN2/8, 256, SMEM_ATT>>>(ea, we1, we2, be2, eidx, outp);
}

// round 5
// speedup vs baseline: 1.2617x; 1.2617x over previous
#include <cuda_runtime.h>
#include <cuda_bf16.h>

// Problem constants (fixed shapes)
#define TN1 32768
#define TN2 32768
#define TDEG 16
#define TIN 128
#define TH 8
#define TD 16
#define THD 128           // H*D

#define APP 132           // smem pitch for A tiles (conflict-free A-frag loads: bank 4g+tg)
#define BPP 136           // smem pitch for B tiles (conflict-free B-frag loads: bank 8tg+g)

// Scratch for projected Q/K/V
__device__ float g_Q[TN2*THD];
__device__ float g_K[TN1*THD];
__device__ float g_V[TN1*THD];

// ---------------------------------------------------------------------------
// tf32 helpers: 3-pass split GEMM via mma.sync.m16n8k8
// ---------------------------------------------------------------------------
__device__ __forceinline__ void tf32_split(float x, unsigned &hi, unsigned &lo) {
    unsigned xb = __float_as_uint(x);
    hi = xb & 0xFFFFE000u;                         // top 10 mantissa bits
    float r = x - __uint_as_float(hi);             // exact residual
    lo = __float_as_uint(r) & 0xFFFFE000u;         // next 10 bits
}

__device__ __forceinline__ void mma8(float* c, const unsigned* a, unsigned b0, unsigned b1) {
    asm volatile(
        "mma.sync.aligned.m16n8k8.row.col.f32.tf32.tf32.f32 "
        "{%0,%1,%2,%3}, {%4,%5,%6,%7}, {%8,%9}, {%0,%1,%2,%3};\n"
        : "+f"(c[0]), "+f"(c[1]), "+f"(c[2]), "+f"(c[3])
        : "r"(a[0]), "r"(a[1]), "r"(a[2]), "r"(a[3]), "r"(b0), "r"(b1));
}

// C[128x128] = A[128x128] * B^T, A in sA (pitch APP, row-major MxK),
// B in sB (pitch BPP, stored [k][n] row-major, i.e. B[n][k] = sB[k*BPP+n]).
// Warp w computes rows 16w..16w+16. c[nt][0..3] per thread:
//   c0 = D[16w+g][8nt+2tg], c1 = +1 col, c2/c3 at row +8.
__device__ __forceinline__ void gemm128_tf32(const float* __restrict__ sA,
                                             const float* __restrict__ sB,
                                             int warp, int lane,
                                             float c[16][4])
{
    const int g = lane >> 2, tg = lane & 3;
    const float* aBase = sA + (warp*16 + g)*APP;
#pragma unroll
    for (int i = 0; i < 16; i++) { c[i][0]=0.f; c[i][1]=0.f; c[i][2]=0.f; c[i][3]=0.f; }

#pragma unroll 1
    for (int k0 = 0; k0 < 128; k0 += 8) {
        unsigned ah[4], al[4];
        tf32_split(aBase[k0+tg],          ah[0], al[0]);   // (g,   tg)
        tf32_split(aBase[8*APP+k0+tg],    ah[1], al[1]);   // (g+8, tg)
        tf32_split(aBase[k0+tg+4],        ah[2], al[2]);   // (g,   tg+4)
        tf32_split(aBase[8*APP+k0+tg+4],  ah[3], al[3]);   // (g+8, tg+4)
        const float* bCol = sB + (k0+tg)*BPP + g;
#pragma unroll
        for (int nt = 0; nt < 16; nt++) {
            unsigned bh0, bl0, bh1, bl1;
            tf32_split(bCol[nt*8],         bh0, bl0);      // B[8nt+g][k0+tg]
            tf32_split(bCol[4*BPP + nt*8], bh1, bl1);      // B[8nt+g][k0+tg+4]
            mma8(c[nt], ah, bh0, bh1);
            mma8(c[nt], ah, bl0, bl1);
            mma8(c[nt], al, bh0, bh1);
        }
    }
}

// ---------------------------------------------------------------------------
// Phase 1: Q/K/V = x @ {wq,wk,wv}, tensor-core 3-pass tf32.
// ---------------------------------------------------------------------------
__global__ __launch_bounds__(256, 1)
void qkv_kernel(const float* __restrict__ x,
                const float* __restrict__ wq,
                const float* __restrict__ wk,
                const float* __restrict__ wv)
{
    extern __shared__ float sm[];
    float* sW = sm;                 // 128 x BPP (weight, [k][n])
    float* sA = sm + 128*BPP;       // 128 x APP (x rows)

    const float* w   = (blockIdx.y == 0) ? wq  : (blockIdx.y == 1) ? wk  : wv;
    float*       dst = (blockIdx.y == 0) ? g_Q : (blockIdx.y == 1) ? g_K : g_V;

    const int tid  = threadIdx.x;
    const int row0 = blockIdx.x * 128;

    // stage weight (row-major [k][n]) and x tile, both via float4
#pragma unroll
    for (int c = 0; c < 16; c++) {
        int f4 = c*256 + tid;
        int r  = f4 >> 5;
        int k4 = f4 & 31;
        float4 v = *(const float4*)(w + (size_t)r*THD + k4*4);
        *(float4*)(sW + r*BPP + k4*4) = v;
        float4 a = *(const float4*)(x + (size_t)(row0 + r)*TIN + k4*4);
        *(float4*)(sA + r*APP + k4*4) = a;
    }
    __syncthreads();

    const int warp = tid >> 5, lane = tid & 31;
    const int g = lane >> 2, tg = lane & 3;

    float c[16][4];
    gemm128_tf32(sA, sW, warp, lane, c);

    // write out
    const int r0 = row0 + warp*16 + g;
#pragma unroll
    for (int nt = 0; nt < 16; nt++) {
        int col = nt*8 + tg*2;
        *(float2*)(dst + (size_t)r0*THD + col)       = make_float2(c[nt][0], c[nt][1]);
        *(float2*)(dst + (size_t)(r0+8)*THD + col)   = make_float2(c[nt][2], c[nt][3]);
    }
}

// ---------------------------------------------------------------------------
// Phase 2: fused attention. e1 GEMM on tensor cores; score/softmax/out
// faithful to the torch reshape: dd = 2h' + d'/8, hh = d'%8.
// ---------------------------------------------------------------------------
__global__ __launch_bounds__(256, 1)
void attn_kernel(const float* __restrict__ ea,
                 const float* __restrict__ we1,
                 const float* __restrict__ we2,
                 const float* __restrict__ be2,
                 const int* __restrict__ eidx,
                 float* __restrict__ outp)
{
    extern __shared__ float sm[];
    float* sW  = sm;                      // 128*BPP : we1 [k][n]
    float* sA  = sW + 128*BPP;            // 128*APP : edge_attr, then e1 (same pitch APP)
    float* sW2 = sA + 128*APP;            // 1024 : we2 [k][8]
    float* sQ  = sW2 + 1024;              // 1024 : q rows for 8 nodes
    float* sE2 = sQ + 1024;               // 1024 : e2 [128 edge][8 h]
    float* sSc = sE2 + 1024;              // 1024 : scores/attn [8 node][8 h'][16 d']
    int*   sNbr = (int*)(sSc + 1024);     // 128  : neighbor ids

    const int tid   = threadIdx.x;
    const int node0 = blockIdx.x * 8;
    const int e0    = node0 * TDEG;

    // ---- stage ----
    ((float4*)sW2)[tid] = ((const float4*)we2)[tid];
    ((float4*)sQ)[tid]  = ((const float4*)(g_Q + (size_t)node0*THD))[tid];
    if (tid < 128) sNbr[tid] = eidx[e0 + tid];
#pragma unroll
    for (int c = 0; c < 16; c++) {
        int f4 = c*256 + tid;
        int r  = f4 >> 5;
        int k4 = f4 & 31;
        float4 wv = *(const float4*)(we1 + (size_t)r*THD + k4*4);
        *(float4*)(sW + r*BPP + k4*4) = wv;
        float4 av = *(const float4*)(ea + (size_t)(e0 + r)*TIN + k4*4);
        *(float4*)(sA + r*APP + k4*4) = av;
    }
    __syncthreads();

    // ---- e2 = ea @ we2 + be2 (reads ALL ea rows; must finish before e1 writeback) ----
    {
        int edge = tid >> 1;
        int h0   = (tid & 1) * 4;
        float acc4[4] = {0.f, 0.f, 0.f, 0.f};
        const float* ar = sA + edge*APP;
#pragma unroll 4
        for (int c = 0; c < 128; c++) {
            float a = ar[c];
            float4 w4 = *(const float4*)(sW2 + c*TH + h0);
            acc4[0] = fmaf(a, w4.x, acc4[0]);
            acc4[1] = fmaf(a, w4.y, acc4[1]);
            acc4[2] = fmaf(a, w4.z, acc4[2]);
            acc4[3] = fmaf(a, w4.w, acc4[3]);
        }
#pragma unroll
        for (int j = 0; j < 4; j++) sE2[edge*TH + h0 + j] = acc4[j] + be2[h0 + j];
    }
    __syncthreads();

    // ---- e1 = ea @ we1 on tensor cores, writeback into sA (own rows only) ----
    const int warp = tid >> 5, lane = tid & 31;
    const int g = lane >> 2, tg = lane & 3;
    {
        float c[16][4];
        gemm128_tf32(sA, sW, warp, lane, c);
        float* rowA = sA + (warp*16 + g)*APP;
        float* rowB = rowA + 8*APP;
#pragma unroll
        for (int nt = 0; nt < 16; nt++) {
            int col = nt*8 + tg*2;
            *(float2*)(rowA + col) = make_float2(c[nt][0], c[nt][1]);
            *(float2*)(rowB + col) = make_float2(c[nt][2], c[nt][3]);
        }
    }
    __syncthreads();

    // ---- scores: 1024 (nl, h', d') tuples, 4 per thread ----
#pragma unroll
    for (int s = 0; s < 4; s++) {
        int u  = tid + s*256;
        int dp = u & 15;
        int hp = (u >> 4) & 7;
        int nl = u >> 7;
        int dd = 2*hp + (dp >> 3);
        int hh = dp & 7;
        int edge_b = nl*16 + dd;
        int nbr = sNbr[edge_b];
        const float* kp = g_K + (size_t)nbr*THD + hh*TD;
        const float* ep = sA + edge_b*APP + hh*TD;
        const float* qp = sQ + nl*THD + hp*TD;
        float sc = sE2[(nl*16 + dp)*TH + hp];
#pragma unroll
        for (int d = 0; d < TD; d += 4) {
            float4 kv = *(const float4*)(kp + d);
            float4 ev = *(const float4*)(ep + d);
            float4 qv = *(const float4*)(qp + d);
            sc += ev.x*kv.x*qv.x;
            sc += ev.y*kv.y*qv.y;
            sc += ev.z*kv.z*qv.z;
            sc += ev.w*kv.w*qv.w;
        }
        sc = fminf(8.0f, fmaxf(-8.0f, sc));
        sSc[nl*128 + hp*16 + dp] = sc;
    }
    __syncthreads();

    // ---- softmax over d'=16 ----
    if (tid < 64) {
        int nl = tid >> 3, h = tid & 7;
        float* p = sSc + nl*128 + h*16;
        float m = p[0];
#pragma unroll
        for (int e = 1; e < 16; e++) m = fmaxf(m, p[e]);
        float ssum = 0.f;
#pragma unroll
        for (int e = 0; e < 16; e++) { float t = __expf(p[e] - m); p[e] = t; ssum += t; }
        float inv = 1.0f / ssum;
#pragma unroll
        for (int e = 0; e < 16; e++) p[e] *= inv;
    }
    __syncthreads();

    // ---- output: out[n,h,k] = sum_d' attn[n,h,d'] * V[nbr(n,d')][h,k] ----
#pragma unroll
    for (int s = 0; s < 4; s++) {
        int u  = tid + s*256;
        int nl = u >> 7;
        int hd = u & 127;
        int h  = hd >> 4;
        const float* ap = sSc + nl*128 + h*16;
        float acco = 0.f;
#pragma unroll
        for (int e = 0; e < 16; e++) {
            int nbr = sNbr[nl*16 + e];
            acco = fmaf(ap[e], g_V[(size_t)nbr*THD + hd], acco);
        }
        outp[(size_t)(node0 + nl)*THD + hd] = acco;
    }
}

// ---------------------------------------------------------------------------
// Launch
// ---------------------------------------------------------------------------
extern "C" void kernel_launch(void* const* d_in, const int* in_sizes, int n_in,
                              void* d_out, int out_size)
{
    const float* x    = (const float*)d_in[0];
    const float* ea   = (const float*)d_in[1];
    const float* wq   = (const float*)d_in[2];
    const float* wk   = (const float*)d_in[3];
    const float* wv   = (const float*)d_in[4];
    const float* we1  = (const float*)d_in[5];
    const float* we2  = (const float*)d_in[6];
    const float* be2  = (const float*)d_in[7];
    const int*   eidx = (const int*)d_in[8];
    float*       outp = (float*)d_out;

    const int SMEM_QKV = (128*BPP + 128*APP) * 4;                    // 137216 B
    const int SMEM_ATT = (128*BPP + 128*APP + 1024*4) * 4 + 128*4;   // 154112 B

    cudaFuncSetAttribute(qkv_kernel,  cudaFuncAttributeMaxDynamicSharedMemorySize, SMEM_QKV);
    cudaFuncSetAttribute(attn_kernel, cudaFuncAttributeMaxDynamicSharedMemorySize, SMEM_ATT);

    qkv_kernel<<<dim3(TN1/128, 3), 256, SMEM_QKV>>>(x, wq, wk, wv);
    attn_kernel<<<TN2/8, 256, SMEM_ATT>>>(ea, we1, we2, be2, eidx, outp);
}